// round 1
// baseline (speedup 1.0000x reference)
#include <cuda_runtime.h>
#include <math.h>

// Problem constants
#define NROWS 65536
#define DD    512
#define NSPLIT 64            // split-K factor for cov
#define CHUNK (NROWS / NSPLIT)   // 1024 rows per split
static __device__ __constant__ float kInvTemp = 0.1f;   // 1/TEMP

typedef unsigned long long u64;

// ---------------------------------------------------------------------------
// f32x2 packed-FMA helpers (full-rate fp32 path on sm_103a)
// ---------------------------------------------------------------------------
__device__ __forceinline__ void ffma2(u64 &d, u64 a, u64 b) {
    asm("fma.rn.f32x2 %0, %1, %2, %0;" : "+l"(d) : "l"(a), "l"(b));
}
__device__ __forceinline__ float2 upk2(u64 v) {
    float2 r;
    asm("mov.b64 {%0, %1}, %2;" : "=f"(r.x), "=f"(r.y) : "l"(v));
    return r;
}

// ---------------------------------------------------------------------------
// Device-global scratch (allocation-free rule: static __device__ arrays)
// ---------------------------------------------------------------------------
__device__ float g_h[(size_t)NROWS * DD];            // current layer pre-activation (134 MB)
__device__ float g_colpart[256 * DD];                // column-sum partials
__device__ float g_mean[DD];                         // column mean
__device__ float g_covpart[(size_t)NSPLIT * DD * DD];// cov split-K partials (67 MB)
__device__ float g_cov[DD * DD];                     // cov (+ I/temp, /N)
__device__ float g_P0[DD * DD];
__device__ float g_P1[DD * DD];
__device__ float g_A1[DD * DD];
__device__ float g_A2[DD * DD];
__device__ float g_scal[2];                          // [0] = 1/tr, [1] = 1/sqrt(tr)

// ---------------------------------------------------------------------------
// Big GEMM:  C[M,512] = op(A)[M,512] @ B[512,512]
//   SUBMEAN: subtract g_mean[k] from A elements (xc = h - mean)
//   SCALE:   multiply output by g_scal[1] (1/sqrt(tr))
// Tiles: 128x128, BK=16, 256 threads, 8x8 per thread (row-paired f32x2).
// Grid: (512/128, M/128) = (4, 512)
// ---------------------------------------------------------------------------
template <bool SUBMEAN, bool SCALE>
__global__ __launch_bounds__(256)
void gemm_big(float* __restrict__ C, const float* __restrict__ A,
              const float* __restrict__ B) {
    __shared__ __align__(16) float As[16][128];   // [k][m]  (transposed)
    __shared__ __align__(16) float Bsd[16][256];  // [k][2n] duplicated pairs

    const int tid = threadIdx.x;
    const int tx = tid & 15;        // 0..15 -> 8 cols each
    const int ty = tid >> 4;        // 0..15 -> 8 rows each

    const float* Ab = A + (size_t)blockIdx.y * 128 * DD;
    const float* Bb = B + blockIdx.x * 128;

    u64 acc[4][8];
#pragma unroll
    for (int p = 0; p < 4; p++)
#pragma unroll
        for (int j = 0; j < 8; j++) acc[p][j] = 0ull;

    for (int k0 = 0; k0 < DD; k0 += 16) {
        // Load A tile 128x16 (transpose into As)
#pragma unroll
        for (int l = 0; l < 2; l++) {
            int idx = tid + l * 256;           // 0..511
            int r = idx >> 2;                  // 0..127
            int c = (idx & 3) << 2;            // 0,4,8,12
            float4 v = *(const float4*)(Ab + (size_t)r * DD + k0 + c);
            if (SUBMEAN) {
                float4 m = *(const float4*)&g_mean[k0 + c];
                v.x -= m.x; v.y -= m.y; v.z -= m.z; v.w -= m.w;
            }
            As[c + 0][r] = v.x; As[c + 1][r] = v.y;
            As[c + 2][r] = v.z; As[c + 3][r] = v.w;
        }
        // Load B tile 16x128, store duplicated pairs
#pragma unroll
        for (int l = 0; l < 2; l++) {
            int idx = tid + l * 256;
            int r = idx >> 5;                  // 0..15
            int c = (idx & 31) << 2;           // 0..124
            float4 v = *(const float4*)(Bb + (size_t)(k0 + r) * DD + c);
            *(float4*)&Bsd[r][2 * c]     = make_float4(v.x, v.x, v.y, v.y);
            *(float4*)&Bsd[r][2 * c + 4] = make_float4(v.z, v.z, v.w, v.w);
        }
        __syncthreads();
#pragma unroll
        for (int kk = 0; kk < 16; kk++) {
            u64 a2[4], b2[8];
#pragma unroll
            for (int p = 0; p < 4; p++)
                a2[p] = *(const u64*)&As[kk][ty * 8 + 2 * p];
#pragma unroll
            for (int j = 0; j < 8; j++)
                b2[j] = *(const u64*)&Bsd[kk][(tx * 8 + j) * 2];
#pragma unroll
            for (int p = 0; p < 4; p++)
#pragma unroll
                for (int j = 0; j < 8; j++) ffma2(acc[p][j], a2[p], b2[j]);
        }
        __syncthreads();
    }

    const float s = SCALE ? g_scal[1] : 1.0f;
    const size_t r0 = (size_t)blockIdx.y * 128 + ty * 8;
    const int c0 = blockIdx.x * 128 + tx * 8;
#pragma unroll
    for (int p = 0; p < 4; p++) {
        float row0[8], row1[8];
#pragma unroll
        for (int j = 0; j < 8; j++) {
            float2 f = upk2(acc[p][j]);
            row0[j] = f.x * s;
            row1[j] = f.y * s;
        }
#pragma unroll
        for (int j = 0; j < 8; j += 4) {
            *(float4*)(C + (r0 + 2 * p) * DD + c0 + j) =
                make_float4(row0[j], row0[j + 1], row0[j + 2], row0[j + 3]);
            *(float4*)(C + (r0 + 2 * p + 1) * DD + c0 + j) =
                make_float4(row1[j], row1[j + 1], row1[j + 2], row1[j + 3]);
        }
    }
}

// ---------------------------------------------------------------------------
// cov partials: covpart[z] = xc_chunk^T @ xc_chunk  (chunk = 1024 rows)
// Output tile 128x128, both operands loaded k-major from g_h with mean-subtract.
// Grid: (4, 4, NSPLIT)
// ---------------------------------------------------------------------------
__global__ __launch_bounds__(256)
void cov_kernel(const float* __restrict__ H) {
    __shared__ __align__(16) float As[16][128];   // [k][i]
    __shared__ __align__(16) float Bsd[16][256];  // [k][2j] duplicated

    const int tid = threadIdx.x;
    const int tx = tid & 15;
    const int ty = tid >> 4;
    const int i0 = blockIdx.y * 128;
    const int j0 = blockIdx.x * 128;
    const size_t n0 = (size_t)blockIdx.z * CHUNK;

    u64 acc[4][8];
#pragma unroll
    for (int p = 0; p < 4; p++)
#pragma unroll
        for (int j = 0; j < 8; j++) acc[p][j] = 0ull;

    for (int k0 = 0; k0 < CHUNK; k0 += 16) {
#pragma unroll
        for (int l = 0; l < 2; l++) {
            int idx = tid + l * 256;
            int r = idx >> 5;                  // 0..15 (row within k-tile)
            int c = (idx & 31) << 2;           // 0..124
            const float* src = H + (n0 + k0 + r) * DD;
            float4 va = *(const float4*)(src + i0 + c);
            float4 ma = *(const float4*)&g_mean[i0 + c];
            va.x -= ma.x; va.y -= ma.y; va.z -= ma.z; va.w -= ma.w;
            *(float4*)&As[r][c] = va;

            float4 vb = *(const float4*)(src + j0 + c);
            float4 mb = *(const float4*)&g_mean[j0 + c];
            vb.x -= mb.x; vb.y -= mb.y; vb.z -= mb.z; vb.w -= mb.w;
            *(float4*)&Bsd[r][2 * c]     = make_float4(vb.x, vb.x, vb.y, vb.y);
            *(float4*)&Bsd[r][2 * c + 4] = make_float4(vb.z, vb.z, vb.w, vb.w);
        }
        __syncthreads();
#pragma unroll
        for (int kk = 0; kk < 16; kk++) {
            u64 a2[4], b2[8];
#pragma unroll
            for (int p = 0; p < 4; p++)
                a2[p] = *(const u64*)&As[kk][ty * 8 + 2 * p];
#pragma unroll
            for (int j = 0; j < 8; j++)
                b2[j] = *(const u64*)&Bsd[kk][(tx * 8 + j) * 2];
#pragma unroll
            for (int p = 0; p < 4; p++)
#pragma unroll
                for (int j = 0; j < 8; j++) ffma2(acc[p][j], a2[p], b2[j]);
        }
        __syncthreads();
    }

    float* out = g_covpart + (size_t)blockIdx.z * DD * DD;
    const int ri = i0 + ty * 8;
    const int cj = j0 + tx * 8;
#pragma unroll
    for (int p = 0; p < 4; p++) {
        float row0[8], row1[8];
#pragma unroll
        for (int j = 0; j < 8; j++) {
            float2 f = upk2(acc[p][j]);
            row0[j] = f.x; row1[j] = f.y;
        }
#pragma unroll
        for (int j = 0; j < 8; j += 4) {
            *(float4*)(out + (size_t)(ri + 2 * p) * DD + cj + j) =
                make_float4(row0[j], row0[j + 1], row0[j + 2], row0[j + 3]);
            *(float4*)(out + (size_t)(ri + 2 * p + 1) * DD + cj + j) =
                make_float4(row1[j], row1[j + 1], row1[j + 2], row1[j + 3]);
        }
    }
}

// ---------------------------------------------------------------------------
// Small GEMM 512x512x512 for Newton-Schulz.
//   MODE 0: C = (A@B) * g_scal[0]          (A1 = P @ S, S = cov/tr)
//   MODE 1: C = A@B                        (A2 = P @ A1)
//   MODE 2: C = 1.5*Pin - 0.5*(A@B)        (P' update)
// Tiles 64x64, BK=16, 256 threads, 4x4 per thread. Grid: (8, 8).
// ---------------------------------------------------------------------------
template <int MODE>
__global__ __launch_bounds__(256)
void gemm_small(float* __restrict__ C, const float* __restrict__ A,
                const float* __restrict__ B, const float* __restrict__ Pin) {
    __shared__ __align__(16) float As[16][64];    // [k][m]
    __shared__ __align__(16) float Bsd[16][128];  // [k][2n] duplicated

    const int tid = threadIdx.x;
    const int tx = tid & 15;   // 4 cols each
    const int ty = tid >> 4;   // 4 rows each
    const int r0 = blockIdx.y * 64;
    const int c0 = blockIdx.x * 64;

    u64 acc[2][4];
#pragma unroll
    for (int p = 0; p < 2; p++)
#pragma unroll
        for (int j = 0; j < 4; j++) acc[p][j] = 0ull;

    for (int k0 = 0; k0 < DD; k0 += 16) {
        {   // A tile 64x16, transpose store
            int r = tid >> 2;                 // 0..63
            int c = (tid & 3) << 2;           // 0,4,8,12
            float4 v = *(const float4*)(A + (size_t)(r0 + r) * DD + k0 + c);
            As[c + 0][r] = v.x; As[c + 1][r] = v.y;
            As[c + 2][r] = v.z; As[c + 3][r] = v.w;
        }
        {   // B tile 16x64, duplicated
            int r = tid >> 4;                 // 0..15
            int c = (tid & 15) << 2;          // 0..60
            float4 v = *(const float4*)(B + (size_t)(k0 + r) * DD + c0 + c);
            *(float4*)&Bsd[r][2 * c]     = make_float4(v.x, v.x, v.y, v.y);
            *(float4*)&Bsd[r][2 * c + 4] = make_float4(v.z, v.z, v.w, v.w);
        }
        __syncthreads();
#pragma unroll
        for (int kk = 0; kk < 16; kk++) {
            u64 a2[2], b2[4];
#pragma unroll
            for (int p = 0; p < 2; p++)
                a2[p] = *(const u64*)&As[kk][ty * 4 + 2 * p];
#pragma unroll
            for (int j = 0; j < 4; j++)
                b2[j] = *(const u64*)&Bsd[kk][(tx * 4 + j) * 2];
#pragma unroll
            for (int p = 0; p < 2; p++)
#pragma unroll
                for (int j = 0; j < 4; j++) ffma2(acc[p][j], a2[p], b2[j]);
        }
        __syncthreads();
    }

    const float sc = (MODE == 0) ? g_scal[0] : 1.0f;
#pragma unroll
    for (int p = 0; p < 2; p++) {
        float row0[4], row1[4];
#pragma unroll
        for (int j = 0; j < 4; j++) {
            float2 f = upk2(acc[p][j]);
            row0[j] = f.x; row1[j] = f.y;
        }
        const int rr0 = r0 + ty * 4 + 2 * p;
        const int cc = c0 + tx * 4;
        if (MODE == 2) {
#pragma unroll
            for (int j = 0; j < 4; j++) {
                row0[j] = 1.5f * Pin[(size_t)rr0 * DD + cc + j] - 0.5f * row0[j];
                row1[j] = 1.5f * Pin[(size_t)(rr0 + 1) * DD + cc + j] - 0.5f * row1[j];
            }
        } else {
#pragma unroll
            for (int j = 0; j < 4; j++) { row0[j] *= sc; row1[j] *= sc; }
        }
        *(float4*)(C + (size_t)rr0 * DD + cc) =
            make_float4(row0[0], row0[1], row0[2], row0[3]);
        *(float4*)(C + (size_t)(rr0 + 1) * DD + cc) =
            make_float4(row1[0], row1[1], row1[2], row1[3]);
    }
}

// ---------------------------------------------------------------------------
// Column-mean reduction (deterministic two-stage, no atomics)
// ---------------------------------------------------------------------------
__global__ void colsum_kernel(const float* __restrict__ H) {
    const int b = blockIdx.x;        // 256 blocks, 256 rows each
    const int t = threadIdx.x;       // 512 threads = 1 column each
    const float* p = H + (size_t)b * 256 * DD + t;
    float s = 0.f;
#pragma unroll 8
    for (int r = 0; r < 256; r++) s += p[(size_t)r * DD];
    g_colpart[b * DD + t] = s;
}

__global__ void mean_final_kernel() {
    const int t = threadIdx.x;       // 512 threads
    float s = 0.f;
#pragma unroll 8
    for (int b = 0; b < 256; b++) s += g_colpart[b * DD + t];
    g_mean[t] = s * (1.0f / (float)NROWS);
}

// cov = (sum of partials)/N + I/temp
__global__ void reduce_cov_kernel() {
    const int idx = blockIdx.x * 1024 + threadIdx.x;   // 256 blocks x 1024
    float s = 0.f;
#pragma unroll 8
    for (int z = 0; z < NSPLIT; z++)
        s += g_covpart[(size_t)z * DD * DD + idx];
    const int i = idx >> 9, j = idx & (DD - 1);
    g_cov[idx] = s * (1.0f / (float)NROWS) + ((i == j) ? kInvTemp : 0.0f);
}

// trace -> 1/tr, 1/sqrt(tr)
__global__ void trace_kernel() {
    __shared__ float sm[512];
    const int t = threadIdx.x;
    sm[t] = g_cov[(size_t)t * DD + t];
    __syncthreads();
    for (int s = 256; s > 0; s >>= 1) {
        if (t < s) sm[t] += sm[t + s];
        __syncthreads();
    }
    if (t == 0) {
        float tr = sm[0];
        g_scal[0] = 1.0f / tr;
        g_scal[1] = 1.0f / sqrtf(tr);
    }
}

// Newton-Schulz iteration 0 done analytically: P1 = 1.5*I - 0.5*S
__global__ void init_P_kernel(float* __restrict__ P) {
    const int idx = blockIdx.x * 1024 + threadIdx.x;
    const int i = idx >> 9, j = idx & (DD - 1);
    P[idx] = ((i == j) ? 1.5f : 0.0f) - 0.5f * g_cov[idx] * g_scal[0];
}

// ---------------------------------------------------------------------------
// Orchestration
// ---------------------------------------------------------------------------
static void run_layer(const float* in, const float* W, float* O,
                      float* ph, float* pcov, float* pP0, float* pP1,
                      float* pA1, float* pA2) {
    dim3 gbig(4, NROWS / 128);
    gemm_big<false, false><<<gbig, 256>>>(ph, in, W);      // h = in @ W
    colsum_kernel<<<256, 512>>>(ph);
    mean_final_kernel<<<1, 512>>>();
    cov_kernel<<<dim3(4, 4, NSPLIT), 256>>>(ph);           // cov partials (mean fused)
    reduce_cov_kernel<<<256, 1024>>>();
    trace_kernel<<<1, 512>>>();
    init_P_kernel<<<256, 1024>>>(pP0);                     // P after NS iter 0

    float* P = pP0;
    float* Pn = pP1;
    for (int it = 1; it < 10; it++) {
        gemm_small<0><<<dim3(8, 8), 256>>>(pA1, P, pcov, nullptr); // A1 = P@cov/tr
        gemm_small<1><<<dim3(8, 8), 256>>>(pA2, P, pA1, nullptr);  // A2 = P@A1
        gemm_small<2><<<dim3(8, 8), 256>>>(Pn, P, pA2, P);         // P' = 1.5P - 0.5 P@A2
        float* t = P; P = Pn; Pn = t;
    }
    // O = (h - mean) @ P * (1/sqrt(tr))
    gemm_big<true, true><<<gbig, 256>>>(O, ph, P);
}

extern "C" void kernel_launch(void* const* d_in, const int* in_sizes, int n_in,
                              void* d_out, int out_size) {
    (void)in_sizes; (void)n_in; (void)out_size;
    const float* x = (const float*)d_in[0];
    const float* W[3] = {(const float*)d_in[1], (const float*)d_in[2],
                         (const float*)d_in[3]};
    float* out = (float*)d_out;

    float *ph, *pcov, *pP0, *pP1, *pA1, *pA2;
    cudaGetSymbolAddress((void**)&ph,   g_h);
    cudaGetSymbolAddress((void**)&pcov, g_cov);
    cudaGetSymbolAddress((void**)&pP0,  g_P0);
    cudaGetSymbolAddress((void**)&pP1,  g_P1);
    cudaGetSymbolAddress((void**)&pA1,  g_A1);
    cudaGetSymbolAddress((void**)&pA2,  g_A2);

    const float* cur = x;
    for (int l = 0; l < 3; l++) {
        float* O = out + (size_t)l * NROWS * DD;
        run_layer(cur, W[l], O, ph, pcov, pP0, pP1, pA1, pA2);
        cur = O;
    }
}

// round 2
// speedup vs baseline: 3.1059x; 3.1059x over previous
#include <cuda_runtime.h>
#include <math.h>

#define NROWS 65536
#define DD    512
#define NSPLIT 64
#define CHUNK (NROWS / NSPLIT)
static __device__ __constant__ float kInvTemp = 0.1f;

typedef unsigned long long u64;

__device__ __forceinline__ void ffma2(u64 &d, u64 a, u64 b) {
    asm("fma.rn.f32x2 %0, %1, %2, %0;" : "+l"(d) : "l"(a), "l"(b));
}
__device__ __forceinline__ float2 upk2(u64 v) {
    float2 r;
    asm("mov.b64 {%0, %1}, %2;" : "=f"(r.x), "=f"(r.y) : "l"(v));
    return r;
}
__device__ __forceinline__ u64 dup2(float x) {
    u64 r;
    asm("mov.b64 %0, {%1, %1};" : "=l"(r) : "f"(x));
    return r;
}

// ---------------------------------------------------------------------------
// Scratch
// ---------------------------------------------------------------------------
__device__ float g_h[(size_t)NROWS * DD];
__device__ float g_colpart[256 * DD];
__device__ float g_mean[DD];
__device__ float g_covpart[(size_t)NSPLIT * DD * DD];
__device__ float g_cov[DD * DD];
__device__ float g_P0[DD * DD];
__device__ float g_P1[DD * DD];
__device__ float g_A1[DD * DD];
__device__ float g_A2[DD * DD];
__device__ float g_scal[2];   // [0]=1/tr  [1]=1/sqrt(tr)

// Upper-triangle 128x128 tile list for cov (4x4 tiles -> 10 pairs)
__constant__ int cTI[10] = {0,0,0,0,1,1,1,2,2,3};
__constant__ int cTJ[10] = {0,1,2,3,1,2,3,2,3,3};

// ---------------------------------------------------------------------------
// Big GEMM: C[M,512] = op(A) @ B, 128x128 tile, BK=16, 256 thr, 8x8/thread.
// acc[r][j]: row r (8 rows), colpair j -> cols 2*(j*16+tx)+{0,1}.
// A duplicated via register mov (broadcast reads), B natural pairs (conflict-free).
// ---------------------------------------------------------------------------
template <bool SUBMEAN, bool SCALE>
__global__ __launch_bounds__(256)
void gemm_big(float* __restrict__ C, const float* __restrict__ A,
              const float* __restrict__ B) {
    __shared__ __align__(16) float As[16][132];   // [k][m] transposed, padded
    __shared__ __align__(16) float Bs[16][128];   // [k][n] natural

    const int tid = threadIdx.x;
    const int tx = tid & 15;
    const int ty = tid >> 4;

    const float* Ab = A + (size_t)blockIdx.y * 128 * DD;
    const float* Bb = B + blockIdx.x * 128;

    u64 acc[8][4];
#pragma unroll
    for (int r = 0; r < 8; r++)
#pragma unroll
        for (int j = 0; j < 4; j++) acc[r][j] = 0ull;

    for (int k0 = 0; k0 < DD; k0 += 16) {
#pragma unroll
        for (int l = 0; l < 2; l++) {               // A tile 128x16 -> transpose
            int idx = tid + l * 256;
            int r = idx >> 2;
            int c = (idx & 3) << 2;
            float4 v = *(const float4*)(Ab + (size_t)r * DD + k0 + c);
            if (SUBMEAN) {
                float4 m = *(const float4*)&g_mean[k0 + c];
                v.x -= m.x; v.y -= m.y; v.z -= m.z; v.w -= m.w;
            }
            As[c + 0][r] = v.x; As[c + 1][r] = v.y;
            As[c + 2][r] = v.z; As[c + 3][r] = v.w;
        }
#pragma unroll
        for (int l = 0; l < 2; l++) {               // B tile 16x128 natural
            int idx = tid + l * 256;
            int r = idx >> 5;
            int c = (idx & 31) << 2;
            *(float4*)&Bs[r][c] = *(const float4*)(Bb + (size_t)(k0 + r) * DD + c);
        }
        __syncthreads();
#pragma unroll
        for (int kk = 0; kk < 16; kk++) {
            float4 a0 = *(const float4*)&As[kk][ty * 8];
            float4 a1 = *(const float4*)&As[kk][ty * 8 + 4];
            u64 a2[8];
            a2[0] = dup2(a0.x); a2[1] = dup2(a0.y);
            a2[2] = dup2(a0.z); a2[3] = dup2(a0.w);
            a2[4] = dup2(a1.x); a2[5] = dup2(a1.y);
            a2[6] = dup2(a1.z); a2[7] = dup2(a1.w);
            u64 b2[4];
#pragma unroll
            for (int j = 0; j < 4; j++)
                b2[j] = *(const u64*)&Bs[kk][(j * 16 + tx) * 2];
#pragma unroll
            for (int r = 0; r < 8; r++)
#pragma unroll
                for (int j = 0; j < 4; j++) ffma2(acc[r][j], a2[r], b2[j]);
        }
        __syncthreads();
    }

    const float s = SCALE ? g_scal[1] : 1.0f;
    const size_t r0 = (size_t)blockIdx.y * 128 + ty * 8;
    const int cb = blockIdx.x * 128;
#pragma unroll
    for (int r = 0; r < 8; r++) {
#pragma unroll
        for (int j = 0; j < 4; j++) {
            float2 f = upk2(acc[r][j]);
            f.x *= s; f.y *= s;
            *(float2*)(C + (r0 + r) * DD + cb + (j * 16 + tx) * 2) = f;
        }
    }
}

// ---------------------------------------------------------------------------
// cov partials, upper-triangle tiles only. Grid: (10, 1, NSPLIT).
// ---------------------------------------------------------------------------
__global__ __launch_bounds__(256)
void cov_kernel(const float* __restrict__ H) {
    __shared__ __align__(16) float As[16][132];   // [k][i] natural (padded)
    __shared__ __align__(16) float Bs[16][128];   // [k][j] natural

    const int tid = threadIdx.x;
    const int tx = tid & 15;
    const int ty = tid >> 4;
    const int i0 = cTI[blockIdx.x] * 128;
    const int j0 = cTJ[blockIdx.x] * 128;
    const size_t n0 = (size_t)blockIdx.z * CHUNK;

    u64 acc[8][4];
#pragma unroll
    for (int r = 0; r < 8; r++)
#pragma unroll
        for (int j = 0; j < 4; j++) acc[r][j] = 0ull;

    for (int k0 = 0; k0 < CHUNK; k0 += 16) {
#pragma unroll
        for (int l = 0; l < 2; l++) {
            int idx = tid + l * 256;
            int r = idx >> 5;
            int c = (idx & 31) << 2;
            const float* src = H + (n0 + k0 + r) * DD;
            float4 va = *(const float4*)(src + i0 + c);
            float4 ma = *(const float4*)&g_mean[i0 + c];
            va.x -= ma.x; va.y -= ma.y; va.z -= ma.z; va.w -= ma.w;
            *(float4*)&As[r][c] = va;
            float4 vb = *(const float4*)(src + j0 + c);
            float4 mb = *(const float4*)&g_mean[j0 + c];
            vb.x -= mb.x; vb.y -= mb.y; vb.z -= mb.z; vb.w -= mb.w;
            *(float4*)&Bs[r][c] = vb;
        }
        __syncthreads();
#pragma unroll
        for (int kk = 0; kk < 16; kk++) {
            float4 a0 = *(const float4*)&As[kk][ty * 8];
            float4 a1 = *(const float4*)&As[kk][ty * 8 + 4];
            u64 a2[8];
            a2[0] = dup2(a0.x); a2[1] = dup2(a0.y);
            a2[2] = dup2(a0.z); a2[3] = dup2(a0.w);
            a2[4] = dup2(a1.x); a2[5] = dup2(a1.y);
            a2[6] = dup2(a1.z); a2[7] = dup2(a1.w);
            u64 b2[4];
#pragma unroll
            for (int j = 0; j < 4; j++)
                b2[j] = *(const u64*)&Bs[kk][(j * 16 + tx) * 2];
#pragma unroll
            for (int r = 0; r < 8; r++)
#pragma unroll
                for (int j = 0; j < 4; j++) ffma2(acc[r][j], a2[r], b2[j]);
        }
        __syncthreads();
    }

    float* out = g_covpart + (size_t)blockIdx.z * DD * DD;
    const int ri = i0 + ty * 8;
#pragma unroll
    for (int r = 0; r < 8; r++) {
#pragma unroll
        for (int j = 0; j < 4; j++) {
            float2 f = upk2(acc[r][j]);
            *(float2*)(out + (size_t)(ri + r) * DD + j0 + (j * 16 + tx) * 2) = f;
        }
    }
}

// ---------------------------------------------------------------------------
// Small GEMM 512^3 for Newton-Schulz. 64x64 tile, 256 thr, 4x4/thread.
//   MODE 0: C = (A@B)*g_scal[0]; MODE 1: C = A@B; MODE 2: C = 1.5*Pin - 0.5*(A@B)
// ---------------------------------------------------------------------------
template <int MODE>
__global__ __launch_bounds__(256)
void gemm_small(float* __restrict__ C, const float* __restrict__ A,
                const float* __restrict__ B, const float* __restrict__ Pin) {
    __shared__ __align__(16) float As[16][68];    // [k][m] transposed, padded
    __shared__ __align__(16) float Bs[16][64];    // [k][n] natural

    const int tid = threadIdx.x;
    const int tx = tid & 15;
    const int ty = tid >> 4;
    const int r0 = blockIdx.y * 64;
    const int c0 = blockIdx.x * 64;

    u64 acc[4][2];
#pragma unroll
    for (int r = 0; r < 4; r++)
#pragma unroll
        for (int j = 0; j < 2; j++) acc[r][j] = 0ull;

    for (int k0 = 0; k0 < DD; k0 += 16) {
        {
            int r = tid >> 2;
            int c = (tid & 3) << 2;
            float4 v = *(const float4*)(A + (size_t)(r0 + r) * DD + k0 + c);
            As[c + 0][r] = v.x; As[c + 1][r] = v.y;
            As[c + 2][r] = v.z; As[c + 3][r] = v.w;
        }
        {
            int r = tid >> 4;
            int c = (tid & 15) << 2;
            *(float4*)&Bs[r][c] = *(const float4*)(B + (size_t)(k0 + r) * DD + c0 + c);
        }
        __syncthreads();
#pragma unroll
        for (int kk = 0; kk < 16; kk++) {
            float4 a0 = *(const float4*)&As[kk][ty * 4];
            u64 a2[4];
            a2[0] = dup2(a0.x); a2[1] = dup2(a0.y);
            a2[2] = dup2(a0.z); a2[3] = dup2(a0.w);
            u64 b2[2];
#pragma unroll
            for (int j = 0; j < 2; j++)
                b2[j] = *(const u64*)&Bs[kk][(j * 16 + tx) * 2];
#pragma unroll
            for (int r = 0; r < 4; r++)
#pragma unroll
                for (int j = 0; j < 2; j++) ffma2(acc[r][j], a2[r], b2[j]);
        }
        __syncthreads();
    }

    const float sc = (MODE == 0) ? g_scal[0] : 1.0f;
#pragma unroll
    for (int r = 0; r < 4; r++) {
#pragma unroll
        for (int j = 0; j < 2; j++) {
            float2 f = upk2(acc[r][j]);
            const size_t row = r0 + ty * 4 + r;
            const int col = c0 + (j * 16 + tx) * 2;
            if (MODE == 2) {
                f.x = 1.5f * Pin[row * DD + col]     - 0.5f * f.x;
                f.y = 1.5f * Pin[row * DD + col + 1] - 0.5f * f.y;
            } else {
                f.x *= sc; f.y *= sc;
            }
            *(float2*)(C + row * DD + col) = f;
        }
    }
}

// ---------------------------------------------------------------------------
// Reductions
// ---------------------------------------------------------------------------
__global__ void colsum_kernel(const float* __restrict__ H) {
    const int b = blockIdx.x;
    const int t = threadIdx.x;
    const float* p = H + (size_t)b * 256 * DD + t;
    float s = 0.f;
#pragma unroll 8
    for (int r = 0; r < 256; r++) s += p[(size_t)r * DD];
    g_colpart[b * DD + t] = s;
}

__global__ void mean_final_kernel() {
    const int t = threadIdx.x;
    float s = 0.f;
#pragma unroll 8
    for (int b = 0; b < 256; b++) s += g_colpart[b * DD + t];
    g_mean[t] = s * (1.0f / (float)NROWS);
}

// cov = sum(partials)/N + I/temp ; mirror lower triangle from upper tiles
__global__ void reduce_cov_kernel() {
    const int idx = blockIdx.x * 1024 + threadIdx.x;
    const int i = idx >> 9, j = idx & (DD - 1);
    const int src = ((i >> 7) <= (j >> 7)) ? (i * DD + j) : (j * DD + i);
    float s = 0.f;
#pragma unroll 8
    for (int z = 0; z < NSPLIT; z++)
        s += g_covpart[(size_t)z * DD * DD + src];
    g_cov[idx] = s * (1.0f / (float)NROWS) + ((i == j) ? kInvTemp : 0.0f);
}

__global__ void trace_kernel() {
    __shared__ float sm[512];
    const int t = threadIdx.x;
    sm[t] = g_cov[(size_t)t * DD + t];
    __syncthreads();
    for (int s = 256; s > 0; s >>= 1) {
        if (t < s) sm[t] += sm[t + s];
        __syncthreads();
    }
    if (t == 0) {
        float tr = sm[0];
        g_scal[0] = 1.0f / tr;
        g_scal[1] = 1.0f / sqrtf(tr);
    }
}

__global__ void init_P_kernel(float* __restrict__ P) {
    const int idx = blockIdx.x * 1024 + threadIdx.x;
    const int i = idx >> 9, j = idx & (DD - 1);
    P[idx] = ((i == j) ? 1.5f : 0.0f) - 0.5f * g_cov[idx] * g_scal[0];
}

// ---------------------------------------------------------------------------
// Orchestration
// ---------------------------------------------------------------------------
static void run_layer(const float* in, const float* W, float* O,
                      float* ph, float* pcov, float* pP0, float* pP1,
                      float* pA1, float* pA2) {
    dim3 gbig(4, NROWS / 128);
    gemm_big<false, false><<<gbig, 256>>>(ph, in, W);
    colsum_kernel<<<256, 512>>>(ph);
    mean_final_kernel<<<1, 512>>>();
    cov_kernel<<<dim3(10, 1, NSPLIT), 256>>>(ph);
    reduce_cov_kernel<<<256, 1024>>>();
    trace_kernel<<<1, 512>>>();
    init_P_kernel<<<256, 1024>>>(pP0);

    float* P = pP0;
    float* Pn = pP1;
    for (int it = 1; it < 10; it++) {
        gemm_small<0><<<dim3(8, 8), 256>>>(pA1, P, pcov, nullptr);
        gemm_small<1><<<dim3(8, 8), 256>>>(pA2, P, pA1, nullptr);
        gemm_small<2><<<dim3(8, 8), 256>>>(Pn, P, pA2, P);
        float* t = P; P = Pn; Pn = t;
    }
    gemm_big<true, true><<<gbig, 256>>>(O, ph, P);
}

extern "C" void kernel_launch(void* const* d_in, const int* in_sizes, int n_in,
                              void* d_out, int out_size) {
    (void)in_sizes; (void)n_in; (void)out_size;
    const float* x = (const float*)d_in[0];
    const float* W[3] = {(const float*)d_in[1], (const float*)d_in[2],
                         (const float*)d_in[3]};
    float* out = (float*)d_out;

    float *ph, *pcov, *pP0, *pP1, *pA1, *pA2;
    cudaGetSymbolAddress((void**)&ph,   g_h);
    cudaGetSymbolAddress((void**)&pcov, g_cov);
    cudaGetSymbolAddress((void**)&pP0,  g_P0);
    cudaGetSymbolAddress((void**)&pP1,  g_P1);
    cudaGetSymbolAddress((void**)&pA1,  g_A1);
    cudaGetSymbolAddress((void**)&pA2,  g_A2);

    const float* cur = x;
    for (int l = 0; l < 3; l++) {
        float* O = out + (size_t)l * NROWS * DD;
        run_layer(cur, W[l], O, ph, pcov, pP0, pP1, pA1, pA2);
        cur = O;
    }
}

// round 4
// speedup vs baseline: 5.2905x; 1.7033x over previous
#include <cuda_runtime.h>
#include <cuda_bf16.h>
#include <math.h>
#include <stdint.h>

#define NROWS 65536
#define DD    512
#define NSPLIT 64
static __device__ __constant__ float kInvTemp = 0.1f;

typedef unsigned long long u64;
typedef __nv_bfloat16 bf16;

// ---------------------------------------------------------------------------
// helpers
// ---------------------------------------------------------------------------
__device__ __forceinline__ uint32_t smem_u32(const void* p) {
    uint32_t a;
    asm("{ .reg .u64 t; cvta.to.shared.u64 t, %1; cvt.u32.u64 %0, t; }"
        : "=r"(a) : "l"(p));
    return a;
}
__device__ __forceinline__ void cp16(uint32_t dst, const void* src) {
    asm volatile("cp.async.cg.shared.global [%0], [%1], 16;"
                 :: "r"(dst), "l"(src) : "memory");
}
__device__ __forceinline__ void cp_commit_wait() {
    asm volatile("cp.async.commit_group;" ::: "memory");
    asm volatile("cp.async.wait_group 0;" ::: "memory");
}
__device__ __forceinline__ void mma16816(float* c, const uint32_t* a,
                                         const uint32_t* b) {
    asm volatile(
        "mma.sync.aligned.m16n8k16.row.col.f32.bf16.bf16.f32 "
        "{%0,%1,%2,%3}, {%4,%5,%6,%7}, {%8,%9}, {%0,%1,%2,%3};"
        : "+f"(c[0]), "+f"(c[1]), "+f"(c[2]), "+f"(c[3])
        : "r"(a[0]), "r"(a[1]), "r"(a[2]), "r"(a[3]), "r"(b[0]), "r"(b[1]));
}
// swizzled smem byte offset for a [128][32] bf16 tile
__device__ __forceinline__ int sw(int r, int k) {
    int s = ((k >> 3) ^ (r & 3) ^ ((r >> 2) & 1)) & 3;
    return r * 64 + s * 16 + (k & 7) * 2;
}
__device__ __forceinline__ void split2(float x, bf16 &hi, bf16 &lo) {
    hi = __float2bfloat16_rn(x);
    lo = __float2bfloat16_rn(x - __bfloat162float(hi));
}
__device__ __forceinline__ uint32_t pack2(bf16 a, bf16 b) {
    __nv_bfloat162 v(a, b);
    return *reinterpret_cast<uint32_t*>(&v);
}

// f32x2 (round-2 proven path for NS)
__device__ __forceinline__ void ffma2(u64 &d, u64 a, u64 b) {
    asm("fma.rn.f32x2 %0, %1, %2, %0;" : "+l"(d) : "l"(a), "l"(b));
}
__device__ __forceinline__ float2 upk2(u64 v) {
    float2 r;
    asm("mov.b64 {%0, %1}, %2;" : "=f"(r.x), "=f"(r.y) : "l"(v));
    return r;
}
__device__ __forceinline__ u64 dup2(float x) {
    u64 r;
    asm("mov.b64 %0, {%1, %1};" : "=l"(r) : "f"(x));
    return r;
}

// ---------------------------------------------------------------------------
// scratch
// ---------------------------------------------------------------------------
__device__ float g_h[(size_t)NROWS * DD];
__device__ float g_colpart[256 * DD];
__device__ float g_mean[DD];
__device__ float g_mc[DD];
__device__ float g_covpart[(size_t)NSPLIT * DD * DD];
__device__ float g_cov[DD * DD];
__device__ float g_P0[DD * DD];
__device__ float g_P1[DD * DD];
__device__ float g_A1[DD * DD];
__device__ float g_A2[DD * DD];
__device__ float g_scal[2];                   // [0]=1/tr [1]=1/sqrt(tr)
__device__ bf16 g_sA0[(size_t)NROWS * DD];    // input splits (A operand)
__device__ bf16 g_sA1[(size_t)NROWS * DD];
__device__ bf16 g_sH0[(size_t)NROWS * DD];    // h splits
__device__ bf16 g_sH1[(size_t)NROWS * DD];
__device__ bf16 g_t0[(size_t)DD * NROWS];     // transposed h splits
__device__ bf16 g_t1[(size_t)DD * NROWS];
__device__ bf16 g_w0[DD * DD];                // W^T / P^T splits
__device__ bf16 g_w1[DD * DD];

__constant__ int cTI[10] = {0,0,0,0,1,1,1,2,2,3};
__constant__ int cTJ[10] = {0,1,2,3,1,2,3,2,3,3};

// ---------------------------------------------------------------------------
// bf16x2-split tensor-core GEMM (mma.sync), 128x128 CTA tile, BK=32.
// acc += A0*B0 + A0*B1 + A1*B0  (fp32 accumulate, deterministic order)
// MODE 0: out = acc (fp32) ; also emit bf16 splits of out into so0/so1
// MODE 1: out = acc*g_scal[1] - g_mc[col] ; also emit splits into so0/so1
// MODE 2: Gram split-K partial -> out + blockIdx.z*DD*DD (upper tiles only)
// ---------------------------------------------------------------------------
template <int MODE>
__global__ __launch_bounds__(256, 2)
void mma_gemm(const bf16* __restrict__ a0g, const bf16* __restrict__ a1g,
              const bf16* __restrict__ b0g, const bf16* __restrict__ b1g,
              float* __restrict__ out,
              bf16* __restrict__ so0, bf16* __restrict__ so1) {
    constexpr int LD  = (MODE == 2) ? NROWS : DD;
    constexpr int NCH = (MODE == 2) ? 32 : 16;

    __shared__ __align__(128) char sm[32768];
    char* smA0 = sm;
    char* smA1 = sm + 8192;
    char* smB0 = sm + 16384;
    char* smB1 = sm + 24576;
    const uint32_t smb = smem_u32(sm);

    const int tid = threadIdx.x;
    const int lane = tid & 31, wid = tid >> 5;
    const int warpRow = wid & 1;        // 2 x 64 rows
    const int warpCol = wid >> 1;       // 4 x 32 cols
    const int g = lane >> 2, t4 = lane & 3;

    int rowBase, colBase;
    size_t kStart;
    float* outp;
    if (MODE == 2) {
        rowBase = cTI[blockIdx.x] * 128;
        colBase = cTJ[blockIdx.x] * 128;
        kStart  = (size_t)blockIdx.z * 1024;
        outp = out + (size_t)blockIdx.z * DD * DD;
    } else {
        rowBase = blockIdx.y * 128;
        colBase = blockIdx.x * 128;
        kStart = 0;
        outp = out;
    }

    float acc[4][4][4];
#pragma unroll
    for (int mi = 0; mi < 4; mi++)
#pragma unroll
        for (int ni = 0; ni < 4; ni++)
#pragma unroll
            for (int q = 0; q < 4; q++) acc[mi][ni][q] = 0.f;

    const int lr = tid >> 2;            // load row 0..63 (+64 on i=1)
    const int lseg = tid & 3;           // k segment
    for (int ch = 0; ch < NCH; ch++) {
        const size_t kpos = kStart + (size_t)ch * 32;
#pragma unroll
        for (int i = 0; i < 2; i++) {
            const int r = lr + i * 64;
            const int soff = sw(r, lseg * 8);
            const size_t ga = (size_t)(rowBase + r) * LD + kpos + lseg * 8;
            const size_t gb = (size_t)(colBase + r) * LD + kpos + lseg * 8;
            cp16(smb + soff,         a0g + ga);
            cp16(smb + 8192 + soff,  a1g + ga);
            cp16(smb + 16384 + soff, b0g + gb);
            cp16(smb + 24576 + soff, b1g + gb);
        }
        cp_commit_wait();
        __syncthreads();

#pragma unroll
        for (int ks = 0; ks < 2; ks++) {
            const int k0 = ks * 16;
            uint32_t fa0[4][4], fa1[4][4];
#pragma unroll
            for (int mi = 0; mi < 4; mi++) {
                const int row = warpRow * 64 + mi * 16 + g;
                fa0[mi][0] = *(const uint32_t*)(smA0 + sw(row,     k0 + t4 * 2));
                fa0[mi][1] = *(const uint32_t*)(smA0 + sw(row + 8, k0 + t4 * 2));
                fa0[mi][2] = *(const uint32_t*)(smA0 + sw(row,     k0 + 8 + t4 * 2));
                fa0[mi][3] = *(const uint32_t*)(smA0 + sw(row + 8, k0 + 8 + t4 * 2));
                fa1[mi][0] = *(const uint32_t*)(smA1 + sw(row,     k0 + t4 * 2));
                fa1[mi][1] = *(const uint32_t*)(smA1 + sw(row + 8, k0 + t4 * 2));
                fa1[mi][2] = *(const uint32_t*)(smA1 + sw(row,     k0 + 8 + t4 * 2));
                fa1[mi][3] = *(const uint32_t*)(smA1 + sw(row + 8, k0 + 8 + t4 * 2));
            }
#pragma unroll
            for (int ni = 0; ni < 4; ni++) {
                const int nr = warpCol * 32 + ni * 8 + g;
                uint32_t fb0[2], fb1[2];
                fb0[0] = *(const uint32_t*)(smB0 + sw(nr, k0 + t4 * 2));
                fb0[1] = *(const uint32_t*)(smB0 + sw(nr, k0 + 8 + t4 * 2));
                fb1[0] = *(const uint32_t*)(smB1 + sw(nr, k0 + t4 * 2));
                fb1[1] = *(const uint32_t*)(smB1 + sw(nr, k0 + 8 + t4 * 2));
#pragma unroll
                for (int mi = 0; mi < 4; mi++) {
                    mma16816(acc[mi][ni], fa0[mi], fb0);
                    mma16816(acc[mi][ni], fa0[mi], fb1);
                    mma16816(acc[mi][ni], fa1[mi], fb0);
                }
            }
        }
        __syncthreads();
    }

    // epilogue
    const float s1 = (MODE == 1) ? g_scal[1] : 1.0f;
#pragma unroll
    for (int mi = 0; mi < 4; mi++) {
        const int row0 = rowBase + warpRow * 64 + mi * 16 + g;
#pragma unroll
        for (int ni = 0; ni < 4; ni++) {
            const int col = colBase + warpCol * 32 + ni * 8 + t4 * 2;
            float v0 = acc[mi][ni][0], v1 = acc[mi][ni][1];
            float v2 = acc[mi][ni][2], v3 = acc[mi][ni][3];
            if (MODE == 1) {
                const float m0 = g_mc[col], m1 = g_mc[col + 1];
                v0 = v0 * s1 - m0; v1 = v1 * s1 - m1;
                v2 = v2 * s1 - m0; v3 = v3 * s1 - m1;
            }
            *(float2*)(outp + (size_t)row0 * DD + col)       = make_float2(v0, v1);
            *(float2*)(outp + (size_t)(row0 + 8) * DD + col) = make_float2(v2, v3);
            if (MODE != 2) {
                bf16 h0, l0, h1, l1, h2, l2, h3, l3;
                split2(v0, h0, l0); split2(v1, h1, l1);
                split2(v2, h2, l2); split2(v3, h3, l3);
                *(uint32_t*)(so0 + (size_t)row0 * DD + col)       = pack2(h0, h1);
                *(uint32_t*)(so1 + (size_t)row0 * DD + col)       = pack2(l0, l1);
                *(uint32_t*)(so0 + (size_t)(row0 + 8) * DD + col) = pack2(h2, h3);
                *(uint32_t*)(so1 + (size_t)(row0 + 8) * DD + col) = pack2(l2, l3);
            }
        }
    }
}

// ---------------------------------------------------------------------------
// split kernels
// ---------------------------------------------------------------------------
__global__ void split_rows2_kernel(const float* __restrict__ in,
                                   bf16* __restrict__ s0, bf16* __restrict__ s1,
                                   int n4) {
    int idx = blockIdx.x * 256 + threadIdx.x;
    if (idx >= n4) return;
    float4 v = ((const float4*)in)[idx];
    bf16 h0, l0, h1, l1, h2, l2, h3, l3;
    split2(v.x, h0, l0); split2(v.y, h1, l1);
    split2(v.z, h2, l2); split2(v.w, h3, l3);
    uint2 p0 = make_uint2(pack2(h0, h1), pack2(h2, h3));
    uint2 p1 = make_uint2(pack2(l0, l1), pack2(l2, l3));
    ((uint2*)s0)[idx] = p0;
    ((uint2*)s1)[idx] = p1;
}

// out[d][n] = src[n][d], split into 2 bf16 planes. grid (rows/32, 16)
__global__ void split_trans2_kernel(const float* __restrict__ src,
                                    bf16* __restrict__ t0, bf16* __restrict__ t1,
                                    int ldout) {
    __shared__ float ts[32][33];
    const int tid = threadIdx.x;
    const int n0 = blockIdx.x * 32;
    const int d0 = blockIdx.y * 32;
    int r = tid >> 3, c = (tid & 7) * 4;
    float4 v = *(const float4*)(src + (size_t)(n0 + r) * DD + d0 + c);
    ts[r][c] = v.x; ts[r][c + 1] = v.y; ts[r][c + 2] = v.z; ts[r][c + 3] = v.w;
    __syncthreads();
    int cc = tid >> 3, rr = (tid & 7) * 4;
    bf16 h[4], l[4];
#pragma unroll
    for (int i = 0; i < 4; i++) split2(ts[rr + i][cc], h[i], l[i]);
    size_t off = (size_t)(d0 + cc) * ldout + n0 + rr;
    *(uint2*)(t0 + off) = make_uint2(pack2(h[0], h[1]), pack2(h[2], h[3]));
    *(uint2*)(t1 + off) = make_uint2(pack2(l[0], l[1]), pack2(l[2], l[3]));
}

// ---------------------------------------------------------------------------
// fp32 small GEMM for Newton-Schulz (round-2 proven)
// ---------------------------------------------------------------------------
__device__ __forceinline__ void small_body(float* __restrict__ C,
                                           const float* __restrict__ A,
                                           const float* __restrict__ B,
                                           const float* __restrict__ Pin,
                                           float sc, bool upd) {
    __shared__ __align__(16) float As[16][68];
    __shared__ __align__(16) float Bs[16][64];
    const int tid = threadIdx.x;
    const int tx = tid & 15;
    const int ty = tid >> 4;
    const int r0 = blockIdx.y * 64;
    const int c0 = blockIdx.x * 64;

    u64 acc[4][2];
#pragma unroll
    for (int r = 0; r < 4; r++)
#pragma unroll
        for (int j = 0; j < 2; j++) acc[r][j] = 0ull;

    for (int k0 = 0; k0 < DD; k0 += 16) {
        {
            int r = tid >> 2, c = (tid & 3) << 2;
            float4 v = *(const float4*)(A + (size_t)(r0 + r) * DD + k0 + c);
            As[c + 0][r] = v.x; As[c + 1][r] = v.y;
            As[c + 2][r] = v.z; As[c + 3][r] = v.w;
        }
        {
            int r = tid >> 4, c = (tid & 15) << 2;
            *(float4*)&Bs[r][c] = *(const float4*)(B + (size_t)(k0 + r) * DD + c0 + c);
        }
        __syncthreads();
#pragma unroll
        for (int kk = 0; kk < 16; kk++) {
            float4 a0 = *(const float4*)&As[kk][ty * 4];
            u64 a2[4];
            a2[0] = dup2(a0.x); a2[1] = dup2(a0.y);
            a2[2] = dup2(a0.z); a2[3] = dup2(a0.w);
            u64 b2[2];
#pragma unroll
            for (int j = 0; j < 2; j++)
                b2[j] = *(const u64*)&Bs[kk][(j * 16 + tx) * 2];
#pragma unroll
            for (int r = 0; r < 4; r++)
#pragma unroll
                for (int j = 0; j < 2; j++) ffma2(acc[r][j], a2[r], b2[j]);
        }
        __syncthreads();
    }
#pragma unroll
    for (int r = 0; r < 4; r++) {
#pragma unroll
        for (int j = 0; j < 2; j++) {
            float2 f = upk2(acc[r][j]);
            const size_t row = r0 + ty * 4 + r;
            const int col = c0 + (j * 16 + tx) * 2;
            if (upd) {
                f.x = 1.5f * Pin[row * DD + col]     - 0.5f * f.x;
                f.y = 1.5f * Pin[row * DD + col + 1] - 0.5f * f.y;
            } else {
                f.x *= sc; f.y *= sc;
            }
            *(float2*)(C + row * DD + col) = f;
        }
    }
}

// z=0: A1 = P@P ; z=1: A2 = (P@cov)*(1/tr)
__global__ __launch_bounds__(256)
void gemm_pair(const float* __restrict__ P) {
    if (blockIdx.z == 0) small_body(g_A1, P, P, nullptr, 1.0f, false);
    else                 small_body(g_A2, P, g_cov, nullptr, g_scal[0], false);
}
// Pn = 1.5*P - 0.5*(A1@A2)
__global__ __launch_bounds__(256)
void gemm_upd(float* __restrict__ Pn, const float* __restrict__ P) {
    small_body(Pn, g_A1, g_A2, P, 1.0f, true);
}

// ---------------------------------------------------------------------------
// reductions
// ---------------------------------------------------------------------------
__global__ void colsum_kernel(const float* __restrict__ H) {
    const int b = blockIdx.x;
    const int t = threadIdx.x;
    const float* p = H + (size_t)b * 256 * DD + t;
    float s = 0.f;
#pragma unroll 8
    for (int r = 0; r < 256; r++) s += p[(size_t)r * DD];
    g_colpart[b * DD + t] = s;
}

__global__ void mean_final_kernel() {
    const int t = threadIdx.x;
    float s = 0.f;
#pragma unroll 8
    for (int b = 0; b < 256; b++) s += g_colpart[b * DD + t];
    g_mean[t] = s * (1.0f / (float)NROWS);
}

// cov = Gram/N - m_i m_j + I/temp (mirror upper tiles)
__global__ void reduce_cov_kernel() {
    const int idx = blockIdx.x * 1024 + threadIdx.x;
    const int i = idx >> 9, j = idx & (DD - 1);
    const int src = ((i >> 7) <= (j >> 7)) ? (i * DD + j) : (j * DD + i);
    float s = 0.f;
#pragma unroll 8
    for (int z = 0; z < NSPLIT; z++)
        s += g_covpart[(size_t)z * DD * DD + src];
    g_cov[idx] = s * (1.0f / (float)NROWS) - g_mean[i] * g_mean[j]
               + ((i == j) ? kInvTemp : 0.0f);
}

__global__ void trace_kernel() {
    __shared__ float sm[512];
    const int t = threadIdx.x;
    sm[t] = g_cov[(size_t)t * DD + t];
    __syncthreads();
    for (int s = 256; s > 0; s >>= 1) {
        if (t < s) sm[t] += sm[t + s];
        __syncthreads();
    }
    if (t == 0) {
        float tr = sm[0];
        g_scal[0] = 1.0f / tr;
        g_scal[1] = 1.0f / sqrtf(tr);
    }
}

__global__ void init_P_kernel(float* __restrict__ P) {
    const int idx = blockIdx.x * 1024 + threadIdx.x;
    const int i = idx >> 9, j = idx & (DD - 1);
    P[idx] = ((i == j) ? 1.5f : 0.0f) - 0.5f * g_cov[idx] * g_scal[0];
}

// g_mc[n] = (sum_k mean[k] * P[k][n]) * (1/sqrt(tr))
__global__ void mc_kernel(const float* __restrict__ P) {
    __shared__ float sm[256];
    const int n = blockIdx.x, t = threadIdx.x;
    float s = g_mean[t] * P[(size_t)t * DD + n]
            + g_mean[t + 256] * P[(size_t)(t + 256) * DD + n];
    sm[t] = s;
    __syncthreads();
    for (int k = 128; k > 0; k >>= 1) {
        if (t < k) sm[t] += sm[t + k];
        __syncthreads();
    }
    if (t == 0) g_mc[n] = sm[0] * g_scal[1];
}

// ---------------------------------------------------------------------------
// orchestration
// ---------------------------------------------------------------------------
extern "C" void kernel_launch(void* const* d_in, const int* in_sizes, int n_in,
                              void* d_out, int out_size) {
    (void)in_sizes; (void)n_in; (void)out_size;
    const float* x = (const float*)d_in[0];
    const float* W[3] = {(const float*)d_in[1], (const float*)d_in[2],
                         (const float*)d_in[3]};
    float* out = (float*)d_out;

    float *ph, *pcovpart, *pP0, *pP1;
    bf16 *psA0, *psA1, *psH0, *psH1, *pt0, *pt1, *pw0, *pw1;
    cudaGetSymbolAddress((void**)&ph, g_h);
    cudaGetSymbolAddress((void**)&pcovpart, g_covpart);
    cudaGetSymbolAddress((void**)&pP0, g_P0);
    cudaGetSymbolAddress((void**)&pP1, g_P1);
    cudaGetSymbolAddress((void**)&psA0, g_sA0);
    cudaGetSymbolAddress((void**)&psA1, g_sA1);
    cudaGetSymbolAddress((void**)&psH0, g_sH0);
    cudaGetSymbolAddress((void**)&psH1, g_sH1);
    cudaGetSymbolAddress((void**)&pt0, g_t0);
    cudaGetSymbolAddress((void**)&pt1, g_t1);
    cudaGetSymbolAddress((void**)&pw0, g_w0);
    cudaGetSymbolAddress((void**)&pw1, g_w1);

    const int N4BIG = NROWS * DD / 4;
    const dim3 gact(4, NROWS / 128);
    const dim3 gcov(10, 1, NSPLIT);

    // layer-0 input splits
    split_rows2_kernel<<<N4BIG / 256, 256>>>(x, psA0, psA1, N4BIG);

    for (int l = 0; l < 3; l++) {
        float* O = out + (size_t)l * NROWS * DD;

        // W^T splits, then h = in @ W (emits h + its splits)
        split_trans2_kernel<<<dim3(16, 16), 256>>>(W[l], pw0, pw1, DD);
        mma_gemm<0><<<gact, 256>>>(psA0, psA1, pw0, pw1, ph, psH0, psH1);

        // mean
        colsum_kernel<<<256, 512>>>(ph);
        mean_final_kernel<<<1, 512>>>();

        // transposed splits of h -> Gram -> cov
        split_trans2_kernel<<<dim3(NROWS / 32, 16), 256>>>(ph, pt0, pt1, NROWS);
        mma_gemm<2><<<gcov, 256>>>(pt0, pt1, pt0, pt1, pcovpart, nullptr, nullptr);
        reduce_cov_kernel<<<256, 1024>>>();
        trace_kernel<<<1, 512>>>();
        init_P_kernel<<<256, 1024>>>(pP0);

        // Newton-Schulz iterations 1..9 (fp32)
        float* P = pP0;
        float* Pn = pP1;
        for (int it = 1; it < 10; it++) {
            gemm_pair<<<dim3(8, 8, 2), 256>>>(P);
            gemm_upd<<<dim3(8, 8), 256>>>(Pn, P);
            float* t = P; P = Pn; Pn = t;
        }

        // O = h@P * 1/sqrt(tr) - mc  (emits O + splits as next layer's input)
        split_trans2_kernel<<<dim3(16, 16), 256>>>(P, pw0, pw1, DD);
        mc_kernel<<<512, 256>>>(P);
        mma_gemm<1><<<gact, 256>>>(psH0, psH1, pw0, pw1, O, psA0, psA1);
    }
}